// round 13
// baseline (speedup 1.0000x reference)
#include <cuda_runtime.h>
#include <cuda_bf16.h>

#define NB 2
#define NN 2048
#define FIN 128
#define FE 64
#define BN2 (NB*NN*NN)                 // 8388608
#define OFF_ROWS 262144
#define OFF_WGT  (262144 + 2*BN2)      // 17039360
#define KS 4
#define SLICE (NB*NN*FE)               // 262144
#define K1_BLOCKS 128
#define EDGE_BLOCKS 128

typedef unsigned int u32;
typedef unsigned long long u64;

__device__ float g_part[KS*NB*NN*FE];             // k-split partials of A@xw
__device__ __align__(16) u32 g_xwt_h[NB*FE*NN/2]; // bf16x2 hi, transposed [b*64+e][n/2]
__device__ __align__(16) u32 g_xwt_l[NB*FE*NN/2]; // bf16x2 lo
__device__ __align__(16) u32 g_csh[NB*NN*FE/2];   // centered x_emb bf16x2 hi [row][e/2]
__device__ __align__(16) u32 g_csl[NB*NN*FE/2];   // centered lo
__device__ float g_cent[NB*FE];
__device__ float g_usq[NB*NN];
__device__ u32 g_maxbits;

// ---------------- warp-MMA helpers (base ISA: sm_80+) ------------------------
__device__ __forceinline__ u32 smem_u32(const void* p) {
    u32 a;
    asm("{ .reg .u64 t; cvta.to.shared.u64 t, %1; cvt.u32.u64 %0, t; }"
        : "=r"(a) : "l"(p));
    return a;
}
__device__ __forceinline__ u32 ldm_addr(u32 base, int row, int col8) {
    return base + row*128 + ((col8 ^ (row & 7)) << 4);
}
__device__ __forceinline__ void ldmx4(u32 a, u32& r0, u32& r1, u32& r2, u32& r3) {
    asm volatile("ldmatrix.sync.aligned.m8n8.x4.shared.b16 {%0,%1,%2,%3}, [%4];"
        : "=r"(r0), "=r"(r1), "=r"(r2), "=r"(r3) : "r"(a) : "memory");
}
__device__ __forceinline__ void mma16816(float* d, const u32* a, u32 b0, u32 b1) {
    asm volatile("mma.sync.aligned.m16n8k16.row.col.f32.bf16.bf16.f32 "
        "{%0,%1,%2,%3}, {%4,%5,%6,%7}, {%8,%9}, {%0,%1,%2,%3};"
        : "+f"(d[0]), "+f"(d[1]), "+f"(d[2]), "+f"(d[3])
        : "r"(a[0]), "r"(a[1]), "r"(a[2]), "r"(a[3]), "r"(b0), "r"(b1));
}
__device__ __forceinline__ void split2(float a, float b, u32& H, u32& L) {
    __nv_bfloat16 ha = __float2bfloat16(a), hb = __float2bfloat16(b);
    float ra = a - __bfloat162float(ha), rb = b - __bfloat162float(hb);
    __nv_bfloat162 hh; hh.x = ha; hh.y = hb;
    __nv_bfloat162 ll; ll.x = __float2bfloat16(ra); ll.y = __float2bfloat16(rb);
    H = *(u32*)&hh; L = *(u32*)&ll;
}

// ---------------- K0: xw = x @ W, emit transposed bf16 hi/lo directly --------
__global__ void k0_xw(const float* __restrict__ x, const float* __restrict__ W) {
    __shared__ float Wsh[FIN*FE];
    __shared__ float xsh[4][FIN];
    __shared__ float res[16][65];
    int tid = threadIdx.x;             // 256
    if (blockIdx.x == 0) {
        if (tid < NB*FE) g_cent[tid] = 0.f;
        if (tid == 128) g_maxbits = 0u;
    }
    for (int i = tid; i < FIN*FE; i += 256) Wsh[i] = W[i];
    int rowBase = blockIdx.x * 16;
    int b = rowBase >> 11, n0 = rowBase & 2047;
    int rloc = tid >> 6, e = tid & 63;
    for (int pass = 0; pass < 4; ++pass) {
        __syncthreads();
        int r0 = rowBase + pass * 4;
        for (int i = tid; i < 4*FIN; i += 256)
            xsh[i >> 7][i & 127] = x[(size_t)r0*FIN + i];
        __syncthreads();
        float acc = 0.f;
        #pragma unroll
        for (int k = 0; k < FIN; ++k)
            acc = fmaf(xsh[rloc][k], Wsh[k*FE + e], acc);
        res[pass*4 + rloc][e] = acc;
    }
    __syncthreads();
    #pragma unroll
    for (int item = tid; item < 512; item += 256) {
        int ee = item >> 3, p = item & 7;
        u32 H, L;
        split2(res[2*p][ee], res[2*p + 1][ee], H, L);
        u32 idx = (u32)(b*FE + ee) * (NN/2) + (u32)(n0 >> 1) + p;
        g_xwt_h[idx] = H;
        g_xwt_l[idx] = L;
    }
}

// edge_index writer (pure index function), grid-strided over EDGE_BLOCKS
__device__ void edge_write(int rb, float* __restrict__ out) {
    long long t = (long long)rb * 256 + threadIdx.x;
    const long long total4 = (2LL*BN2) >> 2;   // 4194304 float4s (64 MB)
    float4* dst = (float4*)(out + OFF_ROWS);
    const long long stride = (long long)EDGE_BLOCKS * 256;
    for (; t < total4; t += stride) {
        long long k = t << 2;
        float4 v;
        if (k < BN2) {
            float r = (float)(k >> 11);              // idx // N
            v = make_float4(r, r, r, r);
        } else {
            long long j = k - BN2;
            float base = (float)((j & 2047) + ((j >> 22) << 11));  // col + N*batch
            v = make_float4(base, base+1.f, base+2.f, base+3.f);
        }
        dst[t] = v;
    }
}

// ---------------- K1x: GEMM partials (blocks 0-127) + edge_index (128+) ------
// Single 48KB stage + register prefetch -> 2 CTAs/SM for latency hiding.
__global__ void __launch_bounds__(256) k1x(const float* __restrict__ A,
                                           float* __restrict__ out) {
    if (blockIdx.x >= K1_BLOCKS) {             // concurrent edge_index store
        edge_write(blockIdx.x - K1_BLOCKS, out);
        return;
    }
    extern __shared__ __align__(16) char dsm[];
    int tid = threadIdx.x, wid = tid >> 5, lane = tid & 31;
    int wy = wid & 3, wx = wid >> 2;
    int sub = lane >> 3, lr = lane & 7;
    int bid = blockIdx.x;
    int b = bid >> 6, ks = (bid >> 4) & 3, i0 = (bid & 15) * 128;

    u32 raw = smem_u32(dsm);
    u32 ab = (raw + 1023u) & ~1023u;
    char* AB = dsm + (ab - raw);

    const float* Ab = A + (size_t)b*NN*NN;
    int kbeg = ks * (NN/KS);

    int arow = tid >> 4, akq = (tid & 15) * 4;
    int xe = tid >> 3, xq = tid & 7;
    float4 aR[8];
    uint4 xhR[2], xlR[2];

    #define K1_LD(k0_) do {                                                    \
        _Pragma("unroll")                                                      \
        for (int v = 0; v < 8; ++v)                                            \
            aR[v] = *(const float4*)(Ab + (size_t)(i0 + arow + v*16)*NN + (k0_) + akq); \
        _Pragma("unroll")                                                      \
        for (int v = 0; v < 2; ++v) {                                          \
            int e_ = xe + v*32;                                                \
            u32 srci = (u32)(b*FE + e_) * (NN/2) + (u32)((k0_) >> 1);          \
            xhR[v] = *((const uint4*)(g_xwt_h + srci) + xq);                   \
            xlR[v] = *((const uint4*)(g_xwt_l + srci) + xq);                   \
        }                                                                      \
    } while (0)

    #define K1_ST(S_) do {                                                     \
        char* AH_ = (S_); char* AL_ = (S_) + 16384;                            \
        char* XH_ = (S_) + 32768; char* XL_ = (S_) + 40960;                    \
        _Pragma("unroll")                                                      \
        for (int v = 0; v < 8; ++v) {                                          \
            int row = arow + v*16;                                             \
            u32 h01, l01, h23, l23;                                            \
            split2(aR[v].x, aR[v].y, h01, l01);                                \
            split2(aR[v].z, aR[v].w, h23, l23);                                \
            int off = row*128 + akq*2; off ^= (off >> 3) & 0x70;               \
            *(u64*)(AH_ + off) = (u64)h01 | ((u64)h23 << 32);                  \
            *(u64*)(AL_ + off) = (u64)l01 | ((u64)l23 << 32);                  \
        }                                                                      \
        _Pragma("unroll")                                                      \
        for (int v = 0; v < 2; ++v) {                                          \
            int e_ = xe + v*32;                                                \
            int off = e_*128 + xq*16; off ^= (off >> 3) & 0x70;                \
            *(uint4*)(XH_ + off) = xhR[v];                                     \
            *(uint4*)(XL_ + off) = xlR[v];                                     \
        }                                                                      \
    } while (0)

    float acc[2][4][4];
    #pragma unroll
    for (int m = 0; m < 2; ++m)
        #pragma unroll
        for (int n = 0; n < 4; ++n)
            #pragma unroll
            for (int q = 0; q < 4; ++q) acc[m][n][q] = 0.f;

    K1_LD(kbeg);
    K1_ST(AB);
    __syncthreads();

    u32 abH = ab, abL = ab + 16384, xbH = ab + 32768, xbL = ab + 40960;
    for (int it = 0; it < 8; ++it) {
        if (it < 7) K1_LD(kbeg + (it + 1) * 64);   // prefetch next chunk to regs
        #pragma unroll
        for (int kp = 0; kp < 4; ++kp) {
            int c8 = kp * 2;
            u32 aH[2][4], aL[2][4];
            #pragma unroll
            for (int mt = 0; mt < 2; ++mt) {
                int r = wy*32 + mt*16 + lr + (sub & 1)*8;
                int cc = c8 + (sub >> 1);
                ldmx4(ldm_addr(abH, r, cc), aH[mt][0], aH[mt][1], aH[mt][2], aH[mt][3]);
                ldmx4(ldm_addr(abL, r, cc), aL[mt][0], aL[mt][1], aL[mt][2], aL[mt][3]);
            }
            #pragma unroll
            for (int np = 0; np < 2; ++np) {
                int rb = wx*32 + np*16 + lr + (sub >> 1)*8;
                int cb = c8 + (sub & 1);
                u32 bh[4], bl[4];
                ldmx4(ldm_addr(xbH, rb, cb), bh[0], bh[1], bh[2], bh[3]);
                ldmx4(ldm_addr(xbL, rb, cb), bl[0], bl[1], bl[2], bl[3]);
                #pragma unroll
                for (int mt = 0; mt < 2; ++mt)
                    #pragma unroll
                    for (int t = 0; t < 2; ++t) {
                        float* d = acc[mt][np*2 + t];
                        mma16816(d, aH[mt], bh[2*t], bh[2*t+1]);
                        mma16816(d, aH[mt], bl[2*t], bl[2*t+1]);
                        mma16816(d, aL[mt], bh[2*t], bh[2*t+1]);
                    }
            }
        }
        if (it < 7) {
            __syncthreads();               // all reads of stage done
            K1_ST(AB);                     // overwrite with prefetched chunk
            __syncthreads();
        }
    }
    float* P = g_part + (size_t)ks*SLICE + (size_t)b*NN*FE;
    #pragma unroll
    for (int mt = 0; mt < 2; ++mt) {
        int gi = i0 + wy*32 + mt*16 + (lane >> 2);
        #pragma unroll
        for (int nt = 0; nt < 4; ++nt) {
            int c = wx*32 + nt*8 + 2*(lane & 3);
            float* d = acc[mt][nt];
            *(float2*)(P + (size_t)gi*FE + c)       = make_float2(d[0], d[1]);
            *(float2*)(P + (size_t)(gi + 8)*FE + c) = make_float2(d[2], d[3]);
        }
    }
}

// ---------------- K1b: x_emb = relu(sum partials + bias), + centroid ---------
__global__ void k1b_bias(const float* __restrict__ bias, float* __restrict__ out) {
    int tid = threadIdx.x;                     // 1024
    int i4 = blockIdx.x * 1024 + tid;          // 64 blocks, 4 floats/thread
    size_t i = (size_t)i4 * 4;
    int e0 = (int)(i & 63);
    float4 v = make_float4(bias[e0], bias[e0+1], bias[e0+2], bias[e0+3]);
    #pragma unroll
    for (int s = 0; s < KS; ++s) {
        float4 p = *(const float4*)(g_part + (size_t)s*SLICE + i);
        v.x += p.x; v.y += p.y; v.z += p.z; v.w += p.w;
    }
    v.x = fmaxf(v.x, 0.f); v.y = fmaxf(v.y, 0.f);
    v.z = fmaxf(v.z, 0.f); v.w = fmaxf(v.w, 0.f);
    *(float4*)(out + i) = v;
    __shared__ float cs[64];
    if (tid < 64) cs[tid] = 0.f;
    __syncthreads();
    float4 w = v;
    w.x += __shfl_down_sync(0xffffffffu, w.x, 16);
    w.y += __shfl_down_sync(0xffffffffu, w.y, 16);
    w.z += __shfl_down_sync(0xffffffffu, w.z, 16);
    w.w += __shfl_down_sync(0xffffffffu, w.w, 16);
    if ((tid & 31) < 16) {
        atomicAdd(&cs[e0],   w.x);
        atomicAdd(&cs[e0+1], w.y);
        atomicAdd(&cs[e0+2], w.z);
        atomicAdd(&cs[e0+3], w.w);
    }
    __syncthreads();
    if (tid < 64) {
        int b = blockIdx.x >> 5;               // 64 rows/block, 32 blocks/batch
        atomicAdd(&g_cent[b*FE + tid], cs[tid] * (1.f/NN));
    }
}

// ---------------- K3: usq + max|x-c| + centered bf16 split -------------------
// grid 128 x 256: 8 lanes per row, 8 floats per thread
__global__ void __launch_bounds__(256) k3_usq(const float* __restrict__ xemb) {
    int tid = threadIdx.x;
    int g = blockIdx.x * 256 + tid;            // 32768 threads
    int row = g >> 3, oct = g & 7;
    int b = row >> 11;
    const float4* src = (const float4*)(xemb + (size_t)row*FE + oct*8);
    float4 t0 = src[0], t1 = src[1];
    const float4* cp = (const float4*)(g_cent + b*FE + oct*8);
    float4 c0 = cp[0], c1 = cp[1];
    float x0 = t0.x - c0.x, x1 = t0.y - c0.y, x2 = t0.z - c0.z, x3 = t0.w - c0.w;
    float x4 = t1.x - c1.x, x5 = t1.y - c1.y, x6 = t1.z - c1.z, x7 = t1.w - c1.w;
    float sq = x0*x0 + x1*x1 + x2*x2 + x3*x3 + x4*x4 + x5*x5 + x6*x6 + x7*x7;
    float av = fmaxf(fmaxf(fmaxf(fabsf(x0), fabsf(x1)), fmaxf(fabsf(x2), fabsf(x3))),
                     fmaxf(fmaxf(fabsf(x4), fabsf(x5)), fmaxf(fabsf(x6), fabsf(x7))));
    uint4 H, L;
    split2(x0, x1, H.x, L.x);
    split2(x2, x3, H.y, L.y);
    split2(x4, x5, H.z, L.z);
    split2(x6, x7, H.w, L.w);
    *(uint4*)(g_csh + (size_t)row*32 + oct*4) = H;
    *(uint4*)(g_csl + (size_t)row*32 + oct*4) = L;
    sq += __shfl_xor_sync(0xffffffffu, sq, 1);
    sq += __shfl_xor_sync(0xffffffffu, sq, 2);
    sq += __shfl_xor_sync(0xffffffffu, sq, 4);
    if (oct == 0) g_usq[row] = sq;
    #pragma unroll
    for (int o = 16; o; o >>= 1)
        av = fmaxf(av, __shfl_xor_sync(0xffffffffu, av, o));
    __shared__ float wm[8];
    if ((tid & 31) == 0) wm[tid >> 5] = av;
    __syncthreads();
    if (tid == 0) {
        float m = wm[0];
        #pragma unroll
        for (int i = 1; i < 8; ++i) m = fmaxf(m, wm[i]);
        atomicMax(&g_maxbits, __float_as_uint(m));
    }
}

__device__ __forceinline__ float sigw(float a, float ui, float uj,
                                      float s2, float T, float TH) {
    float dd = fmaxf(s2 * (ui + uj - 2.f*a), 0.f);
    float z = T * (TH - dd);
    return __fdividef(1.f, 1.f + __expf(-z));
}

// ---------------- K5: Gram via warp-MMA + distances + sigmoid ----------------
__global__ void __launch_bounds__(256) k5_mma(const float* __restrict__ temp,
                                              const float* __restrict__ thr,
                                              float* __restrict__ out) {
    extern __shared__ __align__(16) char dsm[];
    __shared__ float usqi[128], usqj[128];
    int tid = threadIdx.x, wid = tid >> 5, lane = tid & 31;
    int wy = wid & 3, wx = wid >> 2;
    int sub = lane >> 3, lr = lane & 7;
    int b = blockIdx.z, i0 = blockIdx.y * 128, j0 = blockIdx.x * 128;

    u32 raw = smem_u32(dsm);
    u32 ab = (raw + 1023u) & ~1023u;
    char* AB = dsm + (ab - raw);
    u32 tiH = ab, tiL = ab + 16384, tjH = ab + 32768, tjL = ab + 49152;

    #pragma unroll
    for (int t = 0; t < 4; ++t) {
        int rb = (t < 2) ? i0 : j0;
        const u32* src = (t & 1) ? g_csl : g_csh;
        char* dst = AB + t*16384;
        #pragma unroll
        for (int v = 0; v < 4; ++v) {
            int idx = tid + v*256;
            int row = idx >> 3, q = idx & 7;
            uint4 val = *((const uint4*)(src + ((size_t)(b*NN + rb + row) << 5)) + q);
            int off = row*128 + q*16; off ^= (off >> 3) & 0x70;
            *(uint4*)(dst + off) = val;
        }
    }
    if (tid < 128) usqi[tid] = g_usq[b*NN + i0 + tid];
    else           usqj[tid-128] = g_usq[b*NN + j0 + (tid-128)];
    __syncthreads();

    float acc[2][8][4];
    #pragma unroll
    for (int m = 0; m < 2; ++m)
        #pragma unroll
        for (int n = 0; n < 8; ++n)
            #pragma unroll
            for (int q = 0; q < 4; ++q) acc[m][n][q] = 0.f;

    #pragma unroll
    for (int kp = 0; kp < 4; ++kp) {
        int c8 = kp * 2;
        u32 aH[2][4], aL[2][4];
        #pragma unroll
        for (int mt = 0; mt < 2; ++mt) {
            int r = wy*32 + mt*16 + lr + (sub & 1)*8;
            int cc = c8 + (sub >> 1);
            ldmx4(ldm_addr(tiH, r, cc), aH[mt][0], aH[mt][1], aH[mt][2], aH[mt][3]);
            ldmx4(ldm_addr(tiL, r, cc), aL[mt][0], aL[mt][1], aL[mt][2], aL[mt][3]);
        }
        #pragma unroll
        for (int np = 0; np < 4; ++np) {
            int rb = wx*64 + np*16 + lr + (sub >> 1)*8;
            int cb = c8 + (sub & 1);
            u32 bh[4], bl[4];
            ldmx4(ldm_addr(tjH, rb, cb), bh[0], bh[1], bh[2], bh[3]);
            ldmx4(ldm_addr(tjL, rb, cb), bl[0], bl[1], bl[2], bl[3]);
            #pragma unroll
            for (int mt = 0; mt < 2; ++mt)
                #pragma unroll
                for (int t = 0; t < 2; ++t) {
                    float* d = acc[mt][np*2 + t];
                    mma16816(d, aH[mt], bh[2*t], bh[2*t+1]);
                    mma16816(d, aH[mt], bl[2*t], bl[2*t+1]);
                    mma16816(d, aL[mt], bh[2*t], bh[2*t+1]);
                }
        }
    }

    float s = 0.9f / __uint_as_float(g_maxbits);
    float s2 = s * s;
    float T = *temp, TH = fabsf(*thr);
    float* WgB = out + OFF_WGT + (size_t)b*NN*NN;
    #pragma unroll
    for (int mt = 0; mt < 2; ++mt) {
        int li = wy*32 + mt*16 + (lane >> 2);
        int gi0 = i0 + li, gi8 = gi0 + 8;
        float ui0 = usqi[li], ui8 = usqi[li + 8];
        size_t w0 = (size_t)gi0*NN + j0, w8 = (size_t)gi8*NN + j0;
        #pragma unroll
        for (int nt = 0; nt < 8; ++nt) {
            int c = wx*64 + nt*8 + 2*(lane & 3);
            float uj0 = usqj[c], uj1 = usqj[c + 1];
            float* d = acc[mt][nt];
            *(float2*)(WgB + w0 + c) = make_float2(sigw(d[0], ui0, uj0, s2, T, TH),
                                                   sigw(d[1], ui0, uj1, s2, T, TH));
            *(float2*)(WgB + w8 + c) = make_float2(sigw(d[2], ui8, uj0, s2, T, TH),
                                                   sigw(d[3], ui8, uj1, s2, T, TH));
        }
    }
}

extern "C" void kernel_launch(void* const* d_in, const int* in_sizes, int n_in,
                              void* d_out, int out_size) {
    const float* x    = (const float*)d_in[0];
    const float* A    = (const float*)d_in[1];
    const float* W    = (const float*)d_in[2];
    const float* bias = (const float*)d_in[3];
    const float* temp = (const float*)d_in[4];
    const float* thr  = (const float*)d_in[5];
    float* out = (float*)d_out;

    cudaFuncSetAttribute(k1x, cudaFuncAttributeMaxDynamicSharedMemorySize, 50176);
    cudaFuncSetAttribute(k5_mma, cudaFuncAttributeMaxDynamicSharedMemorySize, 66560);

    k0_xw<<<NB*NN/16, 256>>>(x, W);
    k1x<<<K1_BLOCKS + EDGE_BLOCKS, 256, 50176>>>(A, out);
    k1b_bias<<<(NB*NN*FE)/4096, 1024>>>(bias, out);
    k3_usq<<<(NB*NN*8)/256, 256>>>(out);
    k5_mma<<<dim3(NN/128, NN/128, NB), 256, 66560>>>(temp, thr, out);
}

// round 14
// speedup vs baseline: 1.0550x; 1.0550x over previous
#include <cuda_runtime.h>
#include <cuda_bf16.h>

#define NB 2
#define NN 2048
#define FIN 128
#define FE 64
#define BN2 (NB*NN*NN)                 // 8388608
#define OFF_ROWS 262144
#define OFF_WGT  (262144 + 2*BN2)      // 17039360
#define KS 8
#define SLICE (NB*NN*FE)               // 262144
#define K1_BLOCKS 256
#define EDGE_BLOCKS 128

typedef unsigned int u32;
typedef unsigned long long u64;

__device__ float g_part[KS*NB*NN*FE];             // k-split partials of A@xw
__device__ __align__(16) u32 g_xwt_h[NB*FE*NN/2]; // bf16x2 hi, transposed [b*64+e][n/2]
__device__ __align__(16) u32 g_xwt_l[NB*FE*NN/2]; // bf16x2 lo
__device__ __align__(16) u32 g_csh[NB*NN*FE/2];   // centered x_emb bf16x2 hi [row][e/2]
__device__ __align__(16) u32 g_csl[NB*NN*FE/2];   // centered lo
__device__ float g_cent[NB*FE];
__device__ float g_usq[NB*NN];
__device__ u32 g_maxbits;

// ---------------- warp-MMA helpers (base ISA: sm_80+) ------------------------
__device__ __forceinline__ u32 smem_u32(const void* p) {
    u32 a;
    asm("{ .reg .u64 t; cvta.to.shared.u64 t, %1; cvt.u32.u64 %0, t; }"
        : "=r"(a) : "l"(p));
    return a;
}
__device__ __forceinline__ u32 ldm_addr(u32 base, int row, int col8) {
    return base + row*128 + ((col8 ^ (row & 7)) << 4);
}
__device__ __forceinline__ void ldmx4(u32 a, u32& r0, u32& r1, u32& r2, u32& r3) {
    asm volatile("ldmatrix.sync.aligned.m8n8.x4.shared.b16 {%0,%1,%2,%3}, [%4];"
        : "=r"(r0), "=r"(r1), "=r"(r2), "=r"(r3) : "r"(a) : "memory");
}
__device__ __forceinline__ void mma16816(float* d, const u32* a, u32 b0, u32 b1) {
    asm volatile("mma.sync.aligned.m16n8k16.row.col.f32.bf16.bf16.f32 "
        "{%0,%1,%2,%3}, {%4,%5,%6,%7}, {%8,%9}, {%0,%1,%2,%3};"
        : "+f"(d[0]), "+f"(d[1]), "+f"(d[2]), "+f"(d[3])
        : "r"(a[0]), "r"(a[1]), "r"(a[2]), "r"(a[3]), "r"(b0), "r"(b1));
}
__device__ __forceinline__ void split2(float a, float b, u32& H, u32& L) {
    __nv_bfloat16 ha = __float2bfloat16(a), hb = __float2bfloat16(b);
    float ra = a - __bfloat162float(ha), rb = b - __bfloat162float(hb);
    __nv_bfloat162 hh; hh.x = ha; hh.y = hb;
    __nv_bfloat162 ll; ll.x = __float2bfloat16(ra); ll.y = __float2bfloat16(rb);
    H = *(u32*)&hh; L = *(u32*)&ll;
}

// ---------------- K0: xw = x @ W, emit transposed bf16 hi/lo directly --------
__global__ void k0_xw(const float* __restrict__ x, const float* __restrict__ W) {
    __shared__ float Wsh[FIN*FE];
    __shared__ float xsh[4][FIN];
    __shared__ float res[16][65];
    int tid = threadIdx.x;             // 256
    if (blockIdx.x == 0) {
        if (tid < NB*FE) g_cent[tid] = 0.f;
        if (tid == 128) g_maxbits = 0u;
    }
    for (int i = tid; i < FIN*FE; i += 256) Wsh[i] = W[i];
    int rowBase = blockIdx.x * 16;
    int b = rowBase >> 11, n0 = rowBase & 2047;
    int rloc = tid >> 6, e = tid & 63;
    for (int pass = 0; pass < 4; ++pass) {
        __syncthreads();
        int r0 = rowBase + pass * 4;
        for (int i = tid; i < 4*FIN; i += 256)
            xsh[i >> 7][i & 127] = x[(size_t)r0*FIN + i];
        __syncthreads();
        float acc = 0.f;
        #pragma unroll
        for (int k = 0; k < FIN; ++k)
            acc = fmaf(xsh[rloc][k], Wsh[k*FE + e], acc);
        res[pass*4 + rloc][e] = acc;
    }
    __syncthreads();
    #pragma unroll
    for (int item = tid; item < 512; item += 256) {
        int ee = item >> 3, p = item & 7;
        u32 H, L;
        split2(res[2*p][ee], res[2*p + 1][ee], H, L);
        u32 idx = (u32)(b*FE + ee) * (NN/2) + (u32)(n0 >> 1) + p;
        g_xwt_h[idx] = H;
        g_xwt_l[idx] = L;
    }
}

// edge_index writer (pure index function), grid-strided over EDGE_BLOCKS
__device__ void edge_write(int rb, float* __restrict__ out) {
    long long t = (long long)rb * 256 + threadIdx.x;
    const long long total4 = (2LL*BN2) >> 2;   // 4194304 float4s (64 MB)
    float4* dst = (float4*)(out + OFF_ROWS);
    const long long stride = (long long)EDGE_BLOCKS * 256;
    for (; t < total4; t += stride) {
        long long k = t << 2;
        float4 v;
        if (k < BN2) {
            float r = (float)(k >> 11);              // idx // N
            v = make_float4(r, r, r, r);
        } else {
            long long j = k - BN2;
            float base = (float)((j & 2047) + ((j >> 22) << 11));  // col + N*batch
            v = make_float4(base, base+1.f, base+2.f, base+3.f);
        }
        dst[t] = v;
    }
}

// ---------------- K1x: GEMM partials (blocks 0-255) + edge_index (256+) ------
// CTA 128x64, k-split 8 (K=256 each), double-buffered 2x48KB stages.
__global__ void __launch_bounds__(256) k1x(const float* __restrict__ A,
                                           float* __restrict__ out) {
    if (blockIdx.x >= K1_BLOCKS) {             // concurrent edge_index store
        edge_write(blockIdx.x - K1_BLOCKS, out);
        return;
    }
    extern __shared__ __align__(16) char dsm[];
    int tid = threadIdx.x, wid = tid >> 5, lane = tid & 31;
    int wy = wid & 3, wx = wid >> 2;
    int sub = lane >> 3, lr = lane & 7;
    int bid = blockIdx.x;
    int b = bid >> 7, ks = (bid >> 4) & 7, i0 = (bid & 15) * 128;

    u32 raw = smem_u32(dsm);
    u32 ab = (raw + 1023u) & ~1023u;
    char* AB = dsm + (ab - raw);

    const float* Ab = A + (size_t)b*NN*NN;
    int kbeg = ks * (NN/KS);

    int arow = tid >> 4, akq = (tid & 15) * 4;
    int xe = tid >> 3, xq = tid & 7;
    float4 aR[8];
    uint4 xhR[2], xlR[2];

    #define K1_LD(k0_) do {                                                    \
        _Pragma("unroll")                                                      \
        for (int v = 0; v < 8; ++v)                                            \
            aR[v] = *(const float4*)(Ab + (size_t)(i0 + arow + v*16)*NN + (k0_) + akq); \
        _Pragma("unroll")                                                      \
        for (int v = 0; v < 2; ++v) {                                          \
            int e_ = xe + v*32;                                                \
            u32 srci = (u32)(b*FE + e_) * (NN/2) + (u32)((k0_) >> 1);          \
            xhR[v] = *((const uint4*)(g_xwt_h + srci) + xq);                   \
            xlR[v] = *((const uint4*)(g_xwt_l + srci) + xq);                   \
        }                                                                      \
    } while (0)

    #define K1_ST(S_) do {                                                     \
        char* AH_ = (S_); char* AL_ = (S_) + 16384;                            \
        char* XH_ = (S_) + 32768; char* XL_ = (S_) + 40960;                    \
        _Pragma("unroll")                                                      \
        for (int v = 0; v < 8; ++v) {                                          \
            int row = arow + v*16;                                             \
            u32 h01, l01, h23, l23;                                            \
            split2(aR[v].x, aR[v].y, h01, l01);                                \
            split2(aR[v].z, aR[v].w, h23, l23);                                \
            int off = row*128 + akq*2; off ^= (off >> 3) & 0x70;               \
            *(u64*)(AH_ + off) = (u64)h01 | ((u64)h23 << 32);                  \
            *(u64*)(AL_ + off) = (u64)l01 | ((u64)l23 << 32);                  \
        }                                                                      \
        _Pragma("unroll")                                                      \
        for (int v = 0; v < 2; ++v) {                                          \
            int e_ = xe + v*32;                                                \
            int off = e_*128 + xq*16; off ^= (off >> 3) & 0x70;                \
            *(uint4*)(XH_ + off) = xhR[v];                                     \
            *(uint4*)(XL_ + off) = xlR[v];                                     \
        }                                                                      \
    } while (0)

    float acc[2][4][4];
    #pragma unroll
    for (int m = 0; m < 2; ++m)
        #pragma unroll
        for (int n = 0; n < 4; ++n)
            #pragma unroll
            for (int q = 0; q < 4; ++q) acc[m][n][q] = 0.f;

    K1_LD(kbeg);
    K1_ST(AB);
    __syncthreads();

    for (int it = 0; it < 4; ++it) {
        if (it < 3) K1_LD(kbeg + (it + 1) * 64);
        u32 sb = ab + (u32)(it & 1) * 49152;
        u32 abH = sb, abL = sb + 16384, xbH = sb + 32768, xbL = sb + 40960;
        #pragma unroll
        for (int kp = 0; kp < 4; ++kp) {
            int c8 = kp * 2;
            u32 aH[2][4], aL[2][4];
            #pragma unroll
            for (int mt = 0; mt < 2; ++mt) {
                int r = wy*32 + mt*16 + lr + (sub & 1)*8;
                int cc = c8 + (sub >> 1);
                ldmx4(ldm_addr(abH, r, cc), aH[mt][0], aH[mt][1], aH[mt][2], aH[mt][3]);
                ldmx4(ldm_addr(abL, r, cc), aL[mt][0], aL[mt][1], aL[mt][2], aL[mt][3]);
            }
            #pragma unroll
            for (int np = 0; np < 2; ++np) {
                int rb = wx*32 + np*16 + lr + (sub >> 1)*8;
                int cb = c8 + (sub & 1);
                u32 bh[4], bl[4];
                ldmx4(ldm_addr(xbH, rb, cb), bh[0], bh[1], bh[2], bh[3]);
                ldmx4(ldm_addr(xbL, rb, cb), bl[0], bl[1], bl[2], bl[3]);
                #pragma unroll
                for (int mt = 0; mt < 2; ++mt)
                    #pragma unroll
                    for (int t = 0; t < 2; ++t) {
                        float* d = acc[mt][np*2 + t];
                        mma16816(d, aH[mt], bh[2*t], bh[2*t+1]);
                        mma16816(d, aH[mt], bl[2*t], bl[2*t+1]);
                        mma16816(d, aL[mt], bh[2*t], bh[2*t+1]);
                    }
            }
        }
        if (it < 3) {
            K1_ST(AB + ((it + 1) & 1) * 49152);
            __syncthreads();
        }
    }
    float* P = g_part + (size_t)ks*SLICE + (size_t)b*NN*FE;
    #pragma unroll
    for (int mt = 0; mt < 2; ++mt) {
        int gi = i0 + wy*32 + mt*16 + (lane >> 2);
        #pragma unroll
        for (int nt = 0; nt < 4; ++nt) {
            int c = wx*32 + nt*8 + 2*(lane & 3);
            float* d = acc[mt][nt];
            *(float2*)(P + (size_t)gi*FE + c)       = make_float2(d[0], d[1]);
            *(float2*)(P + (size_t)(gi + 8)*FE + c) = make_float2(d[2], d[3]);
        }
    }
}

// ---------------- K1b: x_emb = relu(sum partials + bias), + centroid ---------
__global__ void k1b_bias(const float* __restrict__ bias, float* __restrict__ out) {
    int tid = threadIdx.x;                     // 1024
    int i4 = blockIdx.x * 1024 + tid;          // 64 blocks, 4 floats/thread
    size_t i = (size_t)i4 * 4;
    int e0 = (int)(i & 63);
    float4 v = make_float4(bias[e0], bias[e0+1], bias[e0+2], bias[e0+3]);
    #pragma unroll
    for (int s = 0; s < KS; ++s) {
        float4 p = *(const float4*)(g_part + (size_t)s*SLICE + i);
        v.x += p.x; v.y += p.y; v.z += p.z; v.w += p.w;
    }
    v.x = fmaxf(v.x, 0.f); v.y = fmaxf(v.y, 0.f);
    v.z = fmaxf(v.z, 0.f); v.w = fmaxf(v.w, 0.f);
    *(float4*)(out + i) = v;
    __shared__ float cs[64];
    if (tid < 64) cs[tid] = 0.f;
    __syncthreads();
    float4 w = v;
    w.x += __shfl_down_sync(0xffffffffu, w.x, 16);
    w.y += __shfl_down_sync(0xffffffffu, w.y, 16);
    w.z += __shfl_down_sync(0xffffffffu, w.z, 16);
    w.w += __shfl_down_sync(0xffffffffu, w.w, 16);
    if ((tid & 31) < 16) {
        atomicAdd(&cs[e0],   w.x);
        atomicAdd(&cs[e0+1], w.y);
        atomicAdd(&cs[e0+2], w.z);
        atomicAdd(&cs[e0+3], w.w);
    }
    __syncthreads();
    if (tid < 64) {
        int b = blockIdx.x >> 5;               // 64 rows/block, 32 blocks/batch
        atomicAdd(&g_cent[b*FE + tid], cs[tid] * (1.f/NN));
    }
}

// ---------------- K3: usq + max|x-c| + centered bf16 split -------------------
// grid 256 x 256: 16 lanes per row, 4 floats per thread (1 float4, 1 uint2 out)
__global__ void __launch_bounds__(256) k3_usq(const float* __restrict__ xemb) {
    int tid = threadIdx.x;
    int g = blockIdx.x * 256 + tid;            // 65536 threads
    int row = g >> 4, q = g & 15;
    int b = row >> 11;
    float4 t0 = *(const float4*)(xemb + (size_t)row*FE + q*4);
    float4 c0 = *(const float4*)(g_cent + b*FE + q*4);
    float x0 = t0.x - c0.x, x1 = t0.y - c0.y, x2 = t0.z - c0.z, x3 = t0.w - c0.w;
    float sq = x0*x0 + x1*x1 + x2*x2 + x3*x3;
    float av = fmaxf(fmaxf(fabsf(x0), fabsf(x1)), fmaxf(fabsf(x2), fabsf(x3)));
    uint2 HL0, HL1;
    split2(x0, x1, HL0.x, HL1.x);
    split2(x2, x3, HL0.y, HL1.y);
    *(uint2*)(g_csh + (size_t)row*32 + q*2) = make_uint2(HL0.x, HL0.y);
    *(uint2*)(g_csl + (size_t)row*32 + q*2) = make_uint2(HL1.x, HL1.y);
    sq += __shfl_xor_sync(0xffffffffu, sq, 1);
    sq += __shfl_xor_sync(0xffffffffu, sq, 2);
    sq += __shfl_xor_sync(0xffffffffu, sq, 4);
    sq += __shfl_xor_sync(0xffffffffu, sq, 8);
    if (q == 0) g_usq[row] = sq;
    #pragma unroll
    for (int o = 16; o; o >>= 1)
        av = fmaxf(av, __shfl_xor_sync(0xffffffffu, av, o));
    __shared__ float wm[8];
    if ((tid & 31) == 0) wm[tid >> 5] = av;
    __syncthreads();
    if (tid == 0) {
        float m = wm[0];
        #pragma unroll
        for (int i = 1; i < 8; ++i) m = fmaxf(m, wm[i]);
        atomicMax(&g_maxbits, __float_as_uint(m));
    }
}

__device__ __forceinline__ float sigw(float a, float ui, float uj,
                                      float s2, float T, float TH) {
    float dd = fmaxf(s2 * (ui + uj - 2.f*a), 0.f);
    float z = T * (TH - dd);
    return __fdividef(1.f, 1.f + __expf(-z));
}

// ---------------- K5: Gram via warp-MMA + distances + sigmoid ----------------
// CTA 128(i) x 64(j), K=64; 48KB smem -> 3-4 CTAs/SM, grid 1024.
__global__ void __launch_bounds__(256) k5_mma(const float* __restrict__ temp,
                                              const float* __restrict__ thr,
                                              float* __restrict__ out) {
    extern __shared__ __align__(16) char dsm[];
    __shared__ float usqi[128], usqj[64];
    int tid = threadIdx.x, wid = tid >> 5, lane = tid & 31;
    int wy = wid & 3, wx = wid >> 2;
    int sub = lane >> 3, lr = lane & 7;
    int b = blockIdx.z, i0 = blockIdx.y * 128, j0 = blockIdx.x * 64;

    u32 raw = smem_u32(dsm);
    u32 ab = (raw + 1023u) & ~1023u;
    char* AB = dsm + (ab - raw);
    u32 tiH = ab, tiL = ab + 16384, tjH = ab + 32768, tjL = ab + 40960;

    #pragma unroll
    for (int t = 0; t < 2; ++t) {      // TiH, TiL: 128 rows x 128 B
        const u32* src = t ? g_csl : g_csh;
        char* dst = AB + t*16384;
        #pragma unroll
        for (int v = 0; v < 4; ++v) {
            int idx = tid + v*256;
            int row = idx >> 3, q = idx & 7;
            uint4 val = *((const uint4*)(src + ((size_t)(b*NN + i0 + row) << 5)) + q);
            int off = row*128 + q*16; off ^= (off >> 3) & 0x70;
            *(uint4*)(dst + off) = val;
        }
    }
    #pragma unroll
    for (int t = 0; t < 2; ++t) {      // TjH, TjL: 64 rows x 128 B
        const u32* src = t ? g_csl : g_csh;
        char* dst = AB + 32768 + t*8192;
        #pragma unroll
        for (int v = 0; v < 2; ++v) {
            int idx = tid + v*256;
            int row = idx >> 3, q = idx & 7;
            uint4 val = *((const uint4*)(src + ((size_t)(b*NN + j0 + row) << 5)) + q);
            int off = row*128 + q*16; off ^= (off >> 3) & 0x70;
            *(uint4*)(dst + off) = val;
        }
    }
    if (tid < 128) usqi[tid] = g_usq[b*NN + i0 + tid];
    else if (tid < 192) usqj[tid-128] = g_usq[b*NN + j0 + (tid-128)];
    __syncthreads();

    float acc[2][4][4];
    #pragma unroll
    for (int m = 0; m < 2; ++m)
        #pragma unroll
        for (int n = 0; n < 4; ++n)
            #pragma unroll
            for (int q = 0; q < 4; ++q) acc[m][n][q] = 0.f;

    #pragma unroll
    for (int kp = 0; kp < 4; ++kp) {
        int c8 = kp * 2;
        u32 aH[2][4], aL[2][4];
        #pragma unroll
        for (int mt = 0; mt < 2; ++mt) {
            int r = wy*32 + mt*16 + lr + (sub & 1)*8;
            int cc = c8 + (sub >> 1);
            ldmx4(ldm_addr(tiH, r, cc), aH[mt][0], aH[mt][1], aH[mt][2], aH[mt][3]);
            ldmx4(ldm_addr(tiL, r, cc), aL[mt][0], aL[mt][1], aL[mt][2], aL[mt][3]);
        }
        #pragma unroll
        for (int np = 0; np < 2; ++np) {
            int rb = wx*32 + np*16 + lr + (sub >> 1)*8;
            int cb = c8 + (sub & 1);
            u32 bh[4], bl[4];
            ldmx4(ldm_addr(tjH, rb, cb), bh[0], bh[1], bh[2], bh[3]);
            ldmx4(ldm_addr(tjL, rb, cb), bl[0], bl[1], bl[2], bl[3]);
            #pragma unroll
            for (int mt = 0; mt < 2; ++mt)
                #pragma unroll
                for (int t = 0; t < 2; ++t) {
                    float* d = acc[mt][np*2 + t];
                    mma16816(d, aH[mt], bh[2*t], bh[2*t+1]);
                    mma16816(d, aH[mt], bl[2*t], bl[2*t+1]);
                    mma16816(d, aL[mt], bh[2*t], bh[2*t+1]);
                }
        }
    }

    float s = 0.9f / __uint_as_float(g_maxbits);
    float s2 = s * s;
    float T = *temp, TH = fabsf(*thr);
    float* WgB = out + OFF_WGT + (size_t)b*NN*NN;
    #pragma unroll
    for (int mt = 0; mt < 2; ++mt) {
        int li = wy*32 + mt*16 + (lane >> 2);
        int gi0 = i0 + li, gi8 = gi0 + 8;
        float ui0 = usqi[li], ui8 = usqi[li + 8];
        size_t w0 = (size_t)gi0*NN + j0, w8 = (size_t)gi8*NN + j0;
        #pragma unroll
        for (int nt = 0; nt < 4; ++nt) {
            int c = wx*32 + nt*8 + 2*(lane & 3);
            float uj0 = usqj[c], uj1 = usqj[c + 1];
            float* d = acc[mt][nt];
            *(float2*)(WgB + w0 + c) = make_float2(sigw(d[0], ui0, uj0, s2, T, TH),
                                                   sigw(d[1], ui0, uj1, s2, T, TH));
            *(float2*)(WgB + w8 + c) = make_float2(sigw(d[2], ui8, uj0, s2, T, TH),
                                                   sigw(d[3], ui8, uj1, s2, T, TH));
        }
    }
}

extern "C" void kernel_launch(void* const* d_in, const int* in_sizes, int n_in,
                              void* d_out, int out_size) {
    const float* x    = (const float*)d_in[0];
    const float* A    = (const float*)d_in[1];
    const float* W    = (const float*)d_in[2];
    const float* bias = (const float*)d_in[3];
    const float* temp = (const float*)d_in[4];
    const float* thr  = (const float*)d_in[5];
    float* out = (float*)d_out;

    cudaFuncSetAttribute(k1x, cudaFuncAttributeMaxDynamicSharedMemorySize, 99328);
    cudaFuncSetAttribute(k5_mma, cudaFuncAttributeMaxDynamicSharedMemorySize, 50176);

    k0_xw<<<NB*NN/16, 256>>>(x, W);
    k1x<<<K1_BLOCKS + EDGE_BLOCKS, 256, 99328>>>(A, out);
    k1b_bias<<<(NB*NN*FE)/4096, 1024>>>(bias, out);
    k3_usq<<<(NB*NN*16)/256, 256>>>(out);
    k5_mma<<<dim3(NN/64, NN/128, NB), 256, 50176>>>(temp, thr, out);
}

// round 15
// speedup vs baseline: 1.0866x; 1.0300x over previous
#include <cuda_runtime.h>
#include <cuda_bf16.h>

#define NB 2
#define NN 2048
#define FIN 128
#define FE 64
#define BN2 (NB*NN*NN)                 // 8388608
#define OFF_ROWS 262144
#define OFF_WGT  (262144 + 2*BN2)      // 17039360
#define KS 4
#define SLICE (NB*NN*FE)               // 262144
#define K1_BLOCKS 128
#define EDGE_BLOCKS 128

typedef unsigned int u32;
typedef unsigned long long u64;

__device__ float g_part[KS*NB*NN*FE];             // k-split partials of A@xw
__device__ __align__(16) u32 g_xwt_h[NB*FE*NN/2]; // bf16x2 hi, transposed [b*64+e][n/2]
__device__ __align__(16) u32 g_xwt_l[NB*FE*NN/2]; // bf16x2 lo
__device__ __align__(16) u32 g_csh[NB*NN*FE/2];   // centered x_emb bf16x2 hi [row][e/2]
__device__ __align__(16) u32 g_csl[NB*NN*FE/2];   // centered lo
__device__ float g_cent[NB*FE];
__device__ float g_usq[NB*NN];
__device__ u32 g_maxbits;

// ---------------- warp-MMA helpers (base ISA: sm_80+) ------------------------
__device__ __forceinline__ u32 smem_u32(const void* p) {
    u32 a;
    asm("{ .reg .u64 t; cvta.to.shared.u64 t, %1; cvt.u32.u64 %0, t; }"
        : "=r"(a) : "l"(p));
    return a;
}
__device__ __forceinline__ u32 ldm_addr(u32 base, int row, int col8) {
    return base + row*128 + ((col8 ^ (row & 7)) << 4);
}
__device__ __forceinline__ void ldmx4(u32 a, u32& r0, u32& r1, u32& r2, u32& r3) {
    asm volatile("ldmatrix.sync.aligned.m8n8.x4.shared.b16 {%0,%1,%2,%3}, [%4];"
        : "=r"(r0), "=r"(r1), "=r"(r2), "=r"(r3) : "r"(a) : "memory");
}
__device__ __forceinline__ void mma16816(float* d, const u32* a, u32 b0, u32 b1) {
    asm volatile("mma.sync.aligned.m16n8k16.row.col.f32.bf16.bf16.f32 "
        "{%0,%1,%2,%3}, {%4,%5,%6,%7}, {%8,%9}, {%0,%1,%2,%3};"
        : "+f"(d[0]), "+f"(d[1]), "+f"(d[2]), "+f"(d[3])
        : "r"(a[0]), "r"(a[1]), "r"(a[2]), "r"(a[3]), "r"(b0), "r"(b1));
}
__device__ __forceinline__ void split2(float a, float b, u32& H, u32& L) {
    __nv_bfloat16 ha = __float2bfloat16(a), hb = __float2bfloat16(b);
    float ra = a - __bfloat162float(ha), rb = b - __bfloat162float(hb);
    __nv_bfloat162 hh; hh.x = ha; hh.y = hb;
    __nv_bfloat162 ll; ll.x = __float2bfloat16(ra); ll.y = __float2bfloat16(rb);
    H = *(u32*)&hh; L = *(u32*)&ll;
}

// ---------------- K0: xw = x @ W, emit transposed bf16 hi/lo directly --------
__global__ void k0_xw(const float* __restrict__ x, const float* __restrict__ W) {
    __shared__ float Wsh[FIN*FE];
    __shared__ float xsh[4][FIN];
    __shared__ float res[16][65];
    int tid = threadIdx.x;             // 256
    if (blockIdx.x == 0) {
        if (tid < NB*FE) g_cent[tid] = 0.f;
        if (tid == 128) g_maxbits = 0u;
    }
    for (int i = tid; i < FIN*FE; i += 256) Wsh[i] = W[i];
    int rowBase = blockIdx.x * 16;
    int b = rowBase >> 11, n0 = rowBase & 2047;
    int rloc = tid >> 6, e = tid & 63;
    for (int pass = 0; pass < 4; ++pass) {
        __syncthreads();
        int r0 = rowBase + pass * 4;
        for (int i = tid; i < 4*FIN; i += 256)
            xsh[i >> 7][i & 127] = x[(size_t)r0*FIN + i];
        __syncthreads();
        float acc = 0.f;
        #pragma unroll
        for (int k = 0; k < FIN; ++k)
            acc = fmaf(xsh[rloc][k], Wsh[k*FE + e], acc);
        res[pass*4 + rloc][e] = acc;
    }
    __syncthreads();
    #pragma unroll
    for (int item = tid; item < 512; item += 256) {
        int ee = item >> 3, p = item & 7;
        u32 H, L;
        split2(res[2*p][ee], res[2*p + 1][ee], H, L);
        u32 idx = (u32)(b*FE + ee) * (NN/2) + (u32)(n0 >> 1) + p;
        g_xwt_h[idx] = H;
        g_xwt_l[idx] = L;
    }
}

// edge_index writer (pure index function), grid-strided over EDGE_BLOCKS
__device__ void edge_write(int rb, float* __restrict__ out) {
    long long t = (long long)rb * 256 + threadIdx.x;
    const long long total4 = (2LL*BN2) >> 2;   // 4194304 float4s (64 MB)
    float4* dst = (float4*)(out + OFF_ROWS);
    const long long stride = (long long)EDGE_BLOCKS * 256;
    for (; t < total4; t += stride) {
        long long k = t << 2;
        float4 v;
        if (k < BN2) {
            float r = (float)(k >> 11);              // idx // N
            v = make_float4(r, r, r, r);
        } else {
            long long j = k - BN2;
            float base = (float)((j & 2047) + ((j >> 22) << 11));  // col + N*batch
            v = make_float4(base, base+1.f, base+2.f, base+3.f);
        }
        dst[t] = v;
    }
}

// ---------------- K1x: GEMM partials (blocks 0-127) + edge_index (128+) ------
__global__ void __launch_bounds__(256) k1x(const float* __restrict__ A,
                                           float* __restrict__ out) {
    if (blockIdx.x >= K1_BLOCKS) {             // concurrent edge_index store
        edge_write(blockIdx.x - K1_BLOCKS, out);
        return;
    }
    extern __shared__ __align__(16) char dsm[];
    int tid = threadIdx.x, wid = tid >> 5, lane = tid & 31;
    int wy = wid & 3, wx = wid >> 2;
    int sub = lane >> 3, lr = lane & 7;
    int bid = blockIdx.x;
    int b = bid >> 6, ks = (bid >> 4) & 3, i0 = (bid & 15) * 128;

    u32 raw = smem_u32(dsm);
    u32 ab = (raw + 1023u) & ~1023u;
    char* AB = dsm + (ab - raw);

    const float* Ab = A + (size_t)b*NN*NN;
    int kbeg = ks * (NN/KS);

    int arow = tid >> 4, akq = (tid & 15) * 4;
    int xe = tid >> 3, xq = tid & 7;
    float4 aR[8];
    uint4 xhR[2], xlR[2];

    #define K1_LD(k0_) do {                                                    \
        _Pragma("unroll")                                                      \
        for (int v = 0; v < 8; ++v)                                            \
            aR[v] = *(const float4*)(Ab + (size_t)(i0 + arow + v*16)*NN + (k0_) + akq); \
        _Pragma("unroll")                                                      \
        for (int v = 0; v < 2; ++v) {                                          \
            int e_ = xe + v*32;                                                \
            u32 srci = (u32)(b*FE + e_) * (NN/2) + (u32)((k0_) >> 1);          \
            xhR[v] = *((const uint4*)(g_xwt_h + srci) + xq);                   \
            xlR[v] = *((const uint4*)(g_xwt_l + srci) + xq);                   \
        }                                                                      \
    } while (0)

    #define K1_ST(S_) do {                                                     \
        char* AH_ = (S_); char* AL_ = (S_) + 16384;                            \
        char* XH_ = (S_) + 32768; char* XL_ = (S_) + 40960;                    \
        _Pragma("unroll")                                                      \
        for (int v = 0; v < 8; ++v) {                                          \
            int row = arow + v*16;                                             \
            u32 h01, l01, h23, l23;                                            \
            split2(aR[v].x, aR[v].y, h01, l01);                                \
            split2(aR[v].z, aR[v].w, h23, l23);                                \
            int off = row*128 + akq*2; off ^= (off >> 3) & 0x70;               \
            *(u64*)(AH_ + off) = (u64)h01 | ((u64)h23 << 32);                  \
            *(u64*)(AL_ + off) = (u64)l01 | ((u64)l23 << 32);                  \
        }                                                                      \
        _Pragma("unroll")                                                      \
        for (int v = 0; v < 2; ++v) {                                          \
            int e_ = xe + v*32;                                                \
            int off = e_*128 + xq*16; off ^= (off >> 3) & 0x70;                \
            *(uint4*)(XH_ + off) = xhR[v];                                     \
            *(uint4*)(XL_ + off) = xlR[v];                                     \
        }                                                                      \
    } while (0)

    float acc[2][4][4];
    #pragma unroll
    for (int m = 0; m < 2; ++m)
        #pragma unroll
        for (int n = 0; n < 4; ++n)
            #pragma unroll
            for (int q = 0; q < 4; ++q) acc[m][n][q] = 0.f;

    K1_LD(kbeg);
    K1_ST(AB);
    __syncthreads();

    for (int it = 0; it < 8; ++it) {
        if (it < 7) K1_LD(kbeg + (it + 1) * 64);
        u32 sb = ab + (u32)(it & 1) * 49152;
        u32 abH = sb, abL = sb + 16384, xbH = sb + 32768, xbL = sb + 40960;
        #pragma unroll
        for (int kp = 0; kp < 4; ++kp) {
            int c8 = kp * 2;
            u32 aH[2][4], aL[2][4];
            #pragma unroll
            for (int mt = 0; mt < 2; ++mt) {
                int r = wy*32 + mt*16 + lr + (sub & 1)*8;
                int cc = c8 + (sub >> 1);
                ldmx4(ldm_addr(abH, r, cc), aH[mt][0], aH[mt][1], aH[mt][2], aH[mt][3]);
                ldmx4(ldm_addr(abL, r, cc), aL[mt][0], aL[mt][1], aL[mt][2], aL[mt][3]);
            }
            #pragma unroll
            for (int np = 0; np < 2; ++np) {
                int rb = wx*32 + np*16 + lr + (sub >> 1)*8;
                int cb = c8 + (sub & 1);
                u32 bh[4], bl[4];
                ldmx4(ldm_addr(xbH, rb, cb), bh[0], bh[1], bh[2], bh[3]);
                ldmx4(ldm_addr(xbL, rb, cb), bl[0], bl[1], bl[2], bl[3]);
                #pragma unroll
                for (int mt = 0; mt < 2; ++mt)
                    #pragma unroll
                    for (int t = 0; t < 2; ++t) {
                        float* d = acc[mt][np*2 + t];
                        mma16816(d, aH[mt], bh[2*t], bh[2*t+1]);
                        mma16816(d, aH[mt], bl[2*t], bl[2*t+1]);
                        mma16816(d, aL[mt], bh[2*t], bh[2*t+1]);
                    }
            }
        }
        if (it < 7) {
            K1_ST(AB + ((it + 1) & 1) * 49152);
            __syncthreads();
        }
    }
    float* P = g_part + (size_t)ks*SLICE + (size_t)b*NN*FE;
    #pragma unroll
    for (int mt = 0; mt < 2; ++mt) {
        int gi = i0 + wy*32 + mt*16 + (lane >> 2);
        #pragma unroll
        for (int nt = 0; nt < 4; ++nt) {
            int c = wx*32 + nt*8 + 2*(lane & 3);
            float* d = acc[mt][nt];
            *(float2*)(P + (size_t)gi*FE + c)       = make_float2(d[0], d[1]);
            *(float2*)(P + (size_t)(gi + 8)*FE + c) = make_float2(d[2], d[3]);
        }
    }
}

// ---------------- K1b: x_emb = relu(sum partials + bias), + centroid ---------
__global__ void k1b_bias(const float* __restrict__ bias, float* __restrict__ out) {
    int tid = threadIdx.x;                     // 1024
    int i4 = blockIdx.x * 1024 + tid;          // 64 blocks, 4 floats/thread
    size_t i = (size_t)i4 * 4;
    int e0 = (int)(i & 63);
    float4 v = make_float4(bias[e0], bias[e0+1], bias[e0+2], bias[e0+3]);
    #pragma unroll
    for (int s = 0; s < KS; ++s) {
        float4 p = *(const float4*)(g_part + (size_t)s*SLICE + i);
        v.x += p.x; v.y += p.y; v.z += p.z; v.w += p.w;
    }
    v.x = fmaxf(v.x, 0.f); v.y = fmaxf(v.y, 0.f);
    v.z = fmaxf(v.z, 0.f); v.w = fmaxf(v.w, 0.f);
    *(float4*)(out + i) = v;
    __shared__ float cs[64];
    if (tid < 64) cs[tid] = 0.f;
    __syncthreads();
    float4 w = v;
    w.x += __shfl_down_sync(0xffffffffu, w.x, 16);
    w.y += __shfl_down_sync(0xffffffffu, w.y, 16);
    w.z += __shfl_down_sync(0xffffffffu, w.z, 16);
    w.w += __shfl_down_sync(0xffffffffu, w.w, 16);
    if ((tid & 31) < 16) {
        atomicAdd(&cs[e0],   w.x);
        atomicAdd(&cs[e0+1], w.y);
        atomicAdd(&cs[e0+2], w.z);
        atomicAdd(&cs[e0+3], w.w);
    }
    __syncthreads();
    if (tid < 64) {
        int b = blockIdx.x >> 5;               // 64 rows/block, 32 blocks/batch
        atomicAdd(&g_cent[b*FE + tid], cs[tid] * (1.f/NN));
    }
}

// ---------------- K3: usq + max|x-c| + centered bf16 split -------------------
// grid 256 x 256: 16 lanes per row, 4 floats per thread
__global__ void __launch_bounds__(256) k3_usq(const float* __restrict__ xemb) {
    int tid = threadIdx.x;
    int g = blockIdx.x * 256 + tid;            // 65536 threads
    int row = g >> 4, q = g & 15;
    int b = row >> 11;
    float4 t0 = *(const float4*)(xemb + (size_t)row*FE + q*4);
    float4 c0 = *(const float4*)(g_cent + b*FE + q*4);
    float x0 = t0.x - c0.x, x1 = t0.y - c0.y, x2 = t0.z - c0.z, x3 = t0.w - c0.w;
    float sq = x0*x0 + x1*x1 + x2*x2 + x3*x3;
    float av = fmaxf(fmaxf(fabsf(x0), fabsf(x1)), fmaxf(fabsf(x2), fabsf(x3)));
    uint2 HL0, HL1;
    split2(x0, x1, HL0.x, HL1.x);
    split2(x2, x3, HL0.y, HL1.y);
    *(uint2*)(g_csh + (size_t)row*32 + q*2) = make_uint2(HL0.x, HL0.y);
    *(uint2*)(g_csl + (size_t)row*32 + q*2) = make_uint2(HL1.x, HL1.y);
    sq += __shfl_xor_sync(0xffffffffu, sq, 1);
    sq += __shfl_xor_sync(0xffffffffu, sq, 2);
    sq += __shfl_xor_sync(0xffffffffu, sq, 4);
    sq += __shfl_xor_sync(0xffffffffu, sq, 8);
    if (q == 0) g_usq[row] = sq;
    #pragma unroll
    for (int o = 16; o; o >>= 1)
        av = fmaxf(av, __shfl_xor_sync(0xffffffffu, av, o));
    __shared__ float wm[8];
    if ((tid & 31) == 0) wm[tid >> 5] = av;
    __syncthreads();
    if (tid == 0) {
        float m = wm[0];
        #pragma unroll
        for (int i = 1; i < 8; ++i) m = fmaxf(m, wm[i]);
        atomicMax(&g_maxbits, __float_as_uint(m));
    }
}

__device__ __forceinline__ float sigw(float a, float ui, float uj,
                                      float s2, float T, float TH) {
    float dd = fmaxf(s2 * (ui + uj - 2.f*a), 0.f);
    float z = T * (TH - dd);
    return __fdividef(1.f, 1.f + __expf(-z));
}

// ---------------- K5: Gram via warp-MMA + distances + sigmoid ----------------
// CTA 128(i) x 64(j), K=64; 48KB smem -> 3 CTAs/SM, grid 1024.
__global__ void __launch_bounds__(256) k5_mma(const float* __restrict__ temp,
                                              const float* __restrict__ thr,
                                              float* __restrict__ out) {
    extern __shared__ __align__(16) char dsm[];
    __shared__ float usqi[128], usqj[64];
    int tid = threadIdx.x, wid = tid >> 5, lane = tid & 31;
    int wy = wid & 3, wx = wid >> 2;
    int sub = lane >> 3, lr = lane & 7;
    int b = blockIdx.z, i0 = blockIdx.y * 128, j0 = blockIdx.x * 64;

    u32 raw = smem_u32(dsm);
    u32 ab = (raw + 1023u) & ~1023u;
    char* AB = dsm + (ab - raw);
    u32 tiH = ab, tiL = ab + 16384, tjH = ab + 32768, tjL = ab + 40960;

    #pragma unroll
    for (int t = 0; t < 2; ++t) {      // TiH, TiL: 128 rows x 128 B
        const u32* src = t ? g_csl : g_csh;
        char* dst = AB + t*16384;
        #pragma unroll
        for (int v = 0; v < 4; ++v) {
            int idx = tid + v*256;
            int row = idx >> 3, q = idx & 7;
            uint4 val = *((const uint4*)(src + ((size_t)(b*NN + i0 + row) << 5)) + q);
            int off = row*128 + q*16; off ^= (off >> 3) & 0x70;
            *(uint4*)(dst + off) = val;
        }
    }
    #pragma unroll
    for (int t = 0; t < 2; ++t) {      // TjH, TjL: 64 rows x 128 B
        const u32* src = t ? g_csl : g_csh;
        char* dst = AB + 32768 + t*8192;
        #pragma unroll
        for (int v = 0; v < 2; ++v) {
            int idx = tid + v*256;
            int row = idx >> 3, q = idx & 7;
            uint4 val = *((const uint4*)(src + ((size_t)(b*NN + j0 + row) << 5)) + q);
            int off = row*128 + q*16; off ^= (off >> 3) & 0x70;
            *(uint4*)(dst + off) = val;
        }
    }
    if (tid < 128) usqi[tid] = g_usq[b*NN + i0 + tid];
    else if (tid < 192) usqj[tid-128] = g_usq[b*NN + j0 + (tid-128)];
    __syncthreads();

    float acc[2][4][4];
    #pragma unroll
    for (int m = 0; m < 2; ++m)
        #pragma unroll
        for (int n = 0; n < 4; ++n)
            #pragma unroll
            for (int q = 0; q < 4; ++q) acc[m][n][q] = 0.f;

    #pragma unroll
    for (int kp = 0; kp < 4; ++kp) {
        int c8 = kp * 2;
        u32 aH[2][4], aL[2][4];
        #pragma unroll
        for (int mt = 0; mt < 2; ++mt) {
            int r = wy*32 + mt*16 + lr + (sub & 1)*8;
            int cc = c8 + (sub >> 1);
            ldmx4(ldm_addr(tiH, r, cc), aH[mt][0], aH[mt][1], aH[mt][2], aH[mt][3]);
            ldmx4(ldm_addr(tiL, r, cc), aL[mt][0], aL[mt][1], aL[mt][2], aL[mt][3]);
        }
        #pragma unroll
        for (int np = 0; np < 2; ++np) {
            int rb = wx*32 + np*16 + lr + (sub >> 1)*8;
            int cb = c8 + (sub & 1);
            u32 bh[4], bl[4];
            ldmx4(ldm_addr(tjH, rb, cb), bh[0], bh[1], bh[2], bh[3]);
            ldmx4(ldm_addr(tjL, rb, cb), bl[0], bl[1], bl[2], bl[3]);
            #pragma unroll
            for (int mt = 0; mt < 2; ++mt)
                #pragma unroll
                for (int t = 0; t < 2; ++t) {
                    float* d = acc[mt][np*2 + t];
                    mma16816(d, aH[mt], bh[2*t], bh[2*t+1]);
                    mma16816(d, aH[mt], bl[2*t], bl[2*t+1]);
                    mma16816(d, aL[mt], bh[2*t], bh[2*t+1]);
                }
        }
    }

    float s = 0.9f / __uint_as_float(g_maxbits);
    float s2 = s * s;
    float T = *temp, TH = fabsf(*thr);
    float* WgB = out + OFF_WGT + (size_t)b*NN*NN;
    #pragma unroll
    for (int mt = 0; mt < 2; ++mt) {
        int li = wy*32 + mt*16 + (lane >> 2);
        int gi0 = i0 + li, gi8 = gi0 + 8;
        float ui0 = usqi[li], ui8 = usqi[li + 8];
        size_t w0 = (size_t)gi0*NN + j0, w8 = (size_t)gi8*NN + j0;
        #pragma unroll
        for (int nt = 0; nt < 4; ++nt) {
            int c = wx*32 + nt*8 + 2*(lane & 3);
            float uj0 = usqj[c], uj1 = usqj[c + 1];
            float* d = acc[mt][nt];
            *(float2*)(WgB + w0 + c) = make_float2(sigw(d[0], ui0, uj0, s2, T, TH),
                                                   sigw(d[1], ui0, uj1, s2, T, TH));
            *(float2*)(WgB + w8 + c) = make_float2(sigw(d[2], ui8, uj0, s2, T, TH),
                                                   sigw(d[3], ui8, uj1, s2, T, TH));
        }
    }
}

extern "C" void kernel_launch(void* const* d_in, const int* in_sizes, int n_in,
                              void* d_out, int out_size) {
    const float* x    = (const float*)d_in[0];
    const float* A    = (const float*)d_in[1];
    const float* W    = (const float*)d_in[2];
    const float* bias = (const float*)d_in[3];
    const float* temp = (const float*)d_in[4];
    const float* thr  = (const float*)d_in[5];
    float* out = (float*)d_out;

    cudaFuncSetAttribute(k1x, cudaFuncAttributeMaxDynamicSharedMemorySize, 99328);
    cudaFuncSetAttribute(k5_mma, cudaFuncAttributeMaxDynamicSharedMemorySize, 50176);

    k0_xw<<<NB*NN/16, 256>>>(x, W);
    k1x<<<K1_BLOCKS + EDGE_BLOCKS, 256, 99328>>>(A, out);
    k1b_bias<<<(NB*NN*FE)/4096, 1024>>>(bias, out);
    k3_usq<<<(NB*NN*16)/256, 256>>>(out);
    k5_mma<<<dim3(NN/64, NN/128, NB), 256, 50176>>>(temp, thr, out);
}

// round 16
// speedup vs baseline: 1.1596x; 1.0671x over previous
#include <cuda_runtime.h>
#include <cuda_bf16.h>

#define NB 2
#define NN 2048
#define FIN 128
#define FE 64
#define BN2 (NB*NN*NN)                 // 8388608
#define OFF_ROWS 262144
#define OFF_WGT  (262144 + 2*BN2)      // 17039360
#define KS 4
#define SLICE (NB*NN*FE)               // 262144
#define K1_BLOCKS 128
#define EDGE_BLOCKS 128

typedef unsigned int u32;
typedef unsigned long long u64;

__device__ float g_part[KS*NB*NN*FE];             // k-split partials of A@xw
__device__ __align__(16) u32 g_xwt_h[NB*FE*NN/2]; // bf16x2 hi, transposed [b*64+e][n/2]
__device__ __align__(16) u32 g_xwt_l[NB*FE*NN/2]; // bf16x2 lo
__device__ __align__(16) u32 g_csh[NB*NN*FE/2];   // centered x_emb bf16x2 hi [row][e/2]
__device__ __align__(16) u32 g_csl[NB*NN*FE/2];   // centered lo
__device__ float g_cent[NB*FE];
__device__ float g_usq[NB*NN];
__device__ u32 g_maxbits;
__device__ u32 g_cnt;                             // grid-barrier counter for k1b3

// ---------------- warp-MMA helpers (base ISA: sm_80+) ------------------------
__device__ __forceinline__ u32 smem_u32(const void* p) {
    u32 a;
    asm("{ .reg .u64 t; cvta.to.shared.u64 t, %1; cvt.u32.u64 %0, t; }"
        : "=r"(a) : "l"(p));
    return a;
}
__device__ __forceinline__ u32 ldm_addr(u32 base, int row, int col8) {
    return base + row*128 + ((col8 ^ (row & 7)) << 4);
}
__device__ __forceinline__ void ldmx4(u32 a, u32& r0, u32& r1, u32& r2, u32& r3) {
    asm volatile("ldmatrix.sync.aligned.m8n8.x4.shared.b16 {%0,%1,%2,%3}, [%4];"
        : "=r"(r0), "=r"(r1), "=r"(r2), "=r"(r3) : "r"(a) : "memory");
}
__device__ __forceinline__ void mma16816(float* d, const u32* a, u32 b0, u32 b1) {
    asm volatile("mma.sync.aligned.m16n8k16.row.col.f32.bf16.bf16.f32 "
        "{%0,%1,%2,%3}, {%4,%5,%6,%7}, {%8,%9}, {%0,%1,%2,%3};"
        : "+f"(d[0]), "+f"(d[1]), "+f"(d[2]), "+f"(d[3])
        : "r"(a[0]), "r"(a[1]), "r"(a[2]), "r"(a[3]), "r"(b0), "r"(b1));
}
// packed bf16 hi/lo split: H = {hi=bf16(b), lo=bf16(a)}, L = residuals
__device__ __forceinline__ void split2(float a, float b, u32& H, u32& L) {
    u32 h;
    asm("cvt.rn.bf16x2.f32 %0, %1, %2;" : "=r"(h) : "f"(b), "f"(a));
    float ha = __uint_as_float(h << 16);
    float hb = __uint_as_float(h & 0xFFFF0000u);
    float ra = a - ha, rb = b - hb;
    u32 l;
    asm("cvt.rn.bf16x2.f32 %0, %1, %2;" : "=r"(l) : "f"(rb), "f"(ra));
    H = h; L = l;
}

// ---------------- K0: xw = x @ W, emit transposed bf16 hi/lo directly --------
__global__ void k0_xw(const float* __restrict__ x, const float* __restrict__ W) {
    __shared__ float Wsh[FIN*FE];
    __shared__ float xsh[4][FIN];
    __shared__ float res[16][65];
    int tid = threadIdx.x;             // 256
    if (blockIdx.x == 0) {
        if (tid < NB*FE) g_cent[tid] = 0.f;
        if (tid == 128) g_maxbits = 0u;
        if (tid == 129) g_cnt = 0u;
    }
    for (int i = tid; i < FIN*FE; i += 256) Wsh[i] = W[i];
    int rowBase = blockIdx.x * 16;
    int b = rowBase >> 11, n0 = rowBase & 2047;
    int rloc = tid >> 6, e = tid & 63;
    for (int pass = 0; pass < 4; ++pass) {
        __syncthreads();
        int r0 = rowBase + pass * 4;
        for (int i = tid; i < 4*FIN; i += 256)
            xsh[i >> 7][i & 127] = x[(size_t)r0*FIN + i];
        __syncthreads();
        float acc = 0.f;
        #pragma unroll
        for (int k = 0; k < FIN; ++k)
            acc = fmaf(xsh[rloc][k], Wsh[k*FE + e], acc);
        res[pass*4 + rloc][e] = acc;
    }
    __syncthreads();
    #pragma unroll
    for (int item = tid; item < 512; item += 256) {
        int ee = item >> 3, p = item & 7;
        u32 H, L;
        split2(res[2*p][ee], res[2*p + 1][ee], H, L);
        u32 idx = (u32)(b*FE + ee) * (NN/2) + (u32)(n0 >> 1) + p;
        g_xwt_h[idx] = H;
        g_xwt_l[idx] = L;
    }
}

// edge_index writer (pure index function), grid-strided over EDGE_BLOCKS
__device__ void edge_write(int rb, float* __restrict__ out) {
    long long t = (long long)rb * 256 + threadIdx.x;
    const long long total4 = (2LL*BN2) >> 2;   // 4194304 float4s (64 MB)
    float4* dst = (float4*)(out + OFF_ROWS);
    const long long stride = (long long)EDGE_BLOCKS * 256;
    for (; t < total4; t += stride) {
        long long k = t << 2;
        float4 v;
        if (k < BN2) {
            float r = (float)(k >> 11);              // idx // N
            v = make_float4(r, r, r, r);
        } else {
            long long j = k - BN2;
            float base = (float)((j & 2047) + ((j >> 22) << 11));  // col + N*batch
            v = make_float4(base, base+1.f, base+2.f, base+3.f);
        }
        dst[t] = v;
    }
}

// ---------------- K1x: GEMM partials (blocks 0-127) + edge_index (128+) ------
__global__ void __launch_bounds__(256) k1x(const float* __restrict__ A,
                                           float* __restrict__ out) {
    if (blockIdx.x >= K1_BLOCKS) {             // concurrent edge_index store
        edge_write(blockIdx.x - K1_BLOCKS, out);
        return;
    }
    extern __shared__ __align__(16) char dsm[];
    int tid = threadIdx.x, wid = tid >> 5, lane = tid & 31;
    int wy = wid & 3, wx = wid >> 2;
    int sub = lane >> 3, lr = lane & 7;
    int bid = blockIdx.x;
    int b = bid >> 6, ks = (bid >> 4) & 3, i0 = (bid & 15) * 128;

    u32 raw = smem_u32(dsm);
    u32 ab = (raw + 1023u) & ~1023u;
    char* AB = dsm + (ab - raw);

    const float* Ab = A + (size_t)b*NN*NN;
    int kbeg = ks * (NN/KS);

    int arow = tid >> 4, akq = (tid & 15) * 4;
    int xe = tid >> 3, xq = tid & 7;
    float4 aR[8];
    uint4 xhR[2], xlR[2];

    #define K1_LD(k0_) do {                                                    \
        _Pragma("unroll")                                                      \
        for (int v = 0; v < 8; ++v)                                            \
            aR[v] = *(const float4*)(Ab + (size_t)(i0 + arow + v*16)*NN + (k0_) + akq); \
        _Pragma("unroll")                                                      \
        for (int v = 0; v < 2; ++v) {                                          \
            int e_ = xe + v*32;                                                \
            u32 srci = (u32)(b*FE + e_) * (NN/2) + (u32)((k0_) >> 1);          \
            xhR[v] = *((const uint4*)(g_xwt_h + srci) + xq);                   \
            xlR[v] = *((const uint4*)(g_xwt_l + srci) + xq);                   \
        }                                                                      \
    } while (0)

    #define K1_ST(S_) do {                                                     \
        char* AH_ = (S_); char* AL_ = (S_) + 16384;                            \
        char* XH_ = (S_) + 32768; char* XL_ = (S_) + 40960;                    \
        _Pragma("unroll")                                                      \
        for (int v = 0; v < 8; ++v) {                                          \
            int row = arow + v*16;                                             \
            u32 h01, l01, h23, l23;                                            \
            split2(aR[v].x, aR[v].y, h01, l01);                                \
            split2(aR[v].z, aR[v].w, h23, l23);                                \
            int off = row*128 + akq*2; off ^= (off >> 3) & 0x70;               \
            *(u64*)(AH_ + off) = (u64)h01 | ((u64)h23 << 32);                  \
            *(u64*)(AL_ + off) = (u64)l01 | ((u64)l23 << 32);                  \
        }                                                                      \
        _Pragma("unroll")                                                      \
        for (int v = 0; v < 2; ++v) {                                          \
            int e_ = xe + v*32;                                                \
            int off = e_*128 + xq*16; off ^= (off >> 3) & 0x70;                \
            *(uint4*)(XH_ + off) = xhR[v];                                     \
            *(uint4*)(XL_ + off) = xlR[v];                                     \
        }                                                                      \
    } while (0)

    float acc[2][4][4];
    #pragma unroll
    for (int m = 0; m < 2; ++m)
        #pragma unroll
        for (int n = 0; n < 4; ++n)
            #pragma unroll
            for (int q = 0; q < 4; ++q) acc[m][n][q] = 0.f;

    K1_LD(kbeg);
    K1_ST(AB);
    __syncthreads();

    for (int it = 0; it < 8; ++it) {
        if (it < 7) K1_LD(kbeg + (it + 1) * 64);
        u32 sb = ab + (u32)(it & 1) * 49152;
        u32 abH = sb, abL = sb + 16384, xbH = sb + 32768, xbL = sb + 40960;
        #pragma unroll
        for (int kp = 0; kp < 4; ++kp) {
            int c8 = kp * 2;
            u32 aH[2][4], aL[2][4];
            #pragma unroll
            for (int mt = 0; mt < 2; ++mt) {
                int r = wy*32 + mt*16 + lr + (sub & 1)*8;
                int cc = c8 + (sub >> 1);
                ldmx4(ldm_addr(abH, r, cc), aH[mt][0], aH[mt][1], aH[mt][2], aH[mt][3]);
                ldmx4(ldm_addr(abL, r, cc), aL[mt][0], aL[mt][1], aL[mt][2], aL[mt][3]);
            }
            #pragma unroll
            for (int np = 0; np < 2; ++np) {
                int rb = wx*32 + np*16 + lr + (sub >> 1)*8;
                int cb = c8 + (sub & 1);
                u32 bh[4], bl[4];
                ldmx4(ldm_addr(xbH, rb, cb), bh[0], bh[1], bh[2], bh[3]);
                ldmx4(ldm_addr(xbL, rb, cb), bl[0], bl[1], bl[2], bl[3]);
                #pragma unroll
                for (int mt = 0; mt < 2; ++mt)
                    #pragma unroll
                    for (int t = 0; t < 2; ++t) {
                        float* d = acc[mt][np*2 + t];
                        mma16816(d, aH[mt], bh[2*t], bh[2*t+1]);
                        mma16816(d, aH[mt], bl[2*t], bl[2*t+1]);
                        mma16816(d, aL[mt], bh[2*t], bh[2*t+1]);
                    }
            }
        }
        if (it < 7) {
            K1_ST(AB + ((it + 1) & 1) * 49152);
            __syncthreads();
        }
    }
    float* P = g_part + (size_t)ks*SLICE + (size_t)b*NN*FE;
    #pragma unroll
    for (int mt = 0; mt < 2; ++mt) {
        int gi = i0 + wy*32 + mt*16 + (lane >> 2);
        #pragma unroll
        for (int nt = 0; nt < 4; ++nt) {
            int c = wx*32 + nt*8 + 2*(lane & 3);
            float* d = acc[mt][nt];
            *(float2*)(P + (size_t)gi*FE + c)       = make_float2(d[0], d[1]);
            *(float2*)(P + (size_t)(gi + 8)*FE + c) = make_float2(d[2], d[3]);
        }
    }
}

// ---------------- K1b3: relu(sum+bias) + centroid | grid barrier | usq/split -
// 128 blocks x 512 threads; each thread owns 4 floats of one row (16 lanes/row).
__global__ void __launch_bounds__(512) k1b3(const float* __restrict__ bias,
                                            float* __restrict__ out) {
    int tid = threadIdx.x;
    int row = blockIdx.x * 32 + (tid >> 4);
    int e0 = (tid & 15) * 4;
    int b = row >> 11;
    size_t i = (size_t)row * FE + e0;
    float4 v = *(const float4*)(bias + e0);
    #pragma unroll
    for (int s = 0; s < KS; ++s) {
        float4 p = *(const float4*)(g_part + (size_t)s*SLICE + i);
        v.x += p.x; v.y += p.y; v.z += p.z; v.w += p.w;
    }
    v.x = fmaxf(v.x, 0.f); v.y = fmaxf(v.y, 0.f);
    v.z = fmaxf(v.z, 0.f); v.w = fmaxf(v.w, 0.f);
    *(float4*)(out + i) = v;

    // block-local centroid partial -> global atomics
    __shared__ float cs[64];
    __shared__ float wm[16];
    if (tid < 64) cs[tid] = 0.f;
    __syncthreads();
    {
        float4 w = v;                          // lanes l and l+16: same e-quad
        w.x += __shfl_down_sync(0xffffffffu, w.x, 16);
        w.y += __shfl_down_sync(0xffffffffu, w.y, 16);
        w.z += __shfl_down_sync(0xffffffffu, w.z, 16);
        w.w += __shfl_down_sync(0xffffffffu, w.w, 16);
        if ((tid & 31) < 16) {
            atomicAdd(&cs[e0],   w.x);
            atomicAdd(&cs[e0+1], w.y);
            atomicAdd(&cs[e0+2], w.z);
            atomicAdd(&cs[e0+3], w.w);
        }
    }
    __syncthreads();
    if (tid < 64) atomicAdd(&g_cent[b*FE + tid], cs[tid] * (1.f/NN));

    // ---- software grid barrier (128 blocks, all resident) ----
    __threadfence();
    __syncthreads();
    if (tid == 0) {
        atomicAdd(&g_cnt, 1u);
        while (*(volatile u32*)&g_cnt < 128u) __nanosleep(64);
    }
    __syncthreads();
    __threadfence();

    // ---- phase 2: centered values from registers ----
    float4 c = *(const float4*)(g_cent + b*FE + e0);
    float x0 = v.x - c.x, x1 = v.y - c.y, x2 = v.z - c.z, x3 = v.w - c.w;
    float sq = x0*x0 + x1*x1 + x2*x2 + x3*x3;
    float av = fmaxf(fmaxf(fabsf(x0), fabsf(x1)), fmaxf(fabsf(x2), fabsf(x3)));
    uint2 H, L;
    split2(x0, x1, H.x, L.x);
    split2(x2, x3, H.y, L.y);
    *(uint2*)(g_csh + (size_t)row*32 + (e0 >> 1)) = H;
    *(uint2*)(g_csl + (size_t)row*32 + (e0 >> 1)) = L;
    sq += __shfl_xor_sync(0xffffffffu, sq, 1);
    sq += __shfl_xor_sync(0xffffffffu, sq, 2);
    sq += __shfl_xor_sync(0xffffffffu, sq, 4);
    sq += __shfl_xor_sync(0xffffffffu, sq, 8);
    if ((tid & 15) == 0) g_usq[row] = sq;
    #pragma unroll
    for (int o = 16; o; o >>= 1)
        av = fmaxf(av, __shfl_xor_sync(0xffffffffu, av, o));
    if ((tid & 31) == 0) wm[tid >> 5] = av;
    __syncthreads();
    if (tid == 0) {
        float m = wm[0];
        #pragma unroll
        for (int i2 = 1; i2 < 16; ++i2) m = fmaxf(m, wm[i2]);
        atomicMax(&g_maxbits, __float_as_uint(m));
    }
}

__device__ __forceinline__ float sigw(float a, float ui, float uj,
                                      float s2, float T, float TH) {
    float dd = fmaxf(s2 * (ui + uj - 2.f*a), 0.f);
    float z = T * (TH - dd);
    return __fdividef(1.f, 1.f + __expf(-z));
}

// ---------------- K5: Gram via warp-MMA + distances + sigmoid ----------------
// CTA 128(i) x 64(j), K=64; 48KB smem -> 3 CTAs/SM, grid 1024.
__global__ void __launch_bounds__(256) k5_mma(const float* __restrict__ temp,
                                              const float* __restrict__ thr,
                                              float* __restrict__ out) {
    extern __shared__ __align__(16) char dsm[];
    __shared__ float usqi[128], usqj[64];
    int tid = threadIdx.x, wid = tid >> 5, lane = tid & 31;
    int wy = wid & 3, wx = wid >> 2;
    int sub = lane >> 3, lr = lane & 7;
    int b = blockIdx.z, i0 = blockIdx.y * 128, j0 = blockIdx.x * 64;

    u32 raw = smem_u32(dsm);
    u32 ab = (raw + 1023u) & ~1023u;
    char* AB = dsm + (ab - raw);
    u32 tiH = ab, tiL = ab + 16384, tjH = ab + 32768, tjL = ab + 40960;

    #pragma unroll
    for (int t = 0; t < 2; ++t) {      // TiH, TiL: 128 rows x 128 B
        const u32* src = t ? g_csl : g_csh;
        char* dst = AB + t*16384;
        #pragma unroll
        for (int v = 0; v < 4; ++v) {
            int idx = tid + v*256;
            int row = idx >> 3, q = idx & 7;
            uint4 val = *((const uint4*)(src + ((size_t)(b*NN + i0 + row) << 5)) + q);
            int off = row*128 + q*16; off ^= (off >> 3) & 0x70;
            *(uint4*)(dst + off) = val;
        }
    }
    #pragma unroll
    for (int t = 0; t < 2; ++t) {      // TjH, TjL: 64 rows x 128 B
        const u32* src = t ? g_csl : g_csh;
        char* dst = AB + 32768 + t*8192;
        #pragma unroll
        for (int v = 0; v < 2; ++v) {
            int idx = tid + v*256;
            int row = idx >> 3, q = idx & 7;
            uint4 val = *((const uint4*)(src + ((size_t)(b*NN + j0 + row) << 5)) + q);
            int off = row*128 + q*16; off ^= (off >> 3) & 0x70;
            *(uint4*)(dst + off) = val;
        }
    }
    if (tid < 128) usqi[tid] = g_usq[b*NN + i0 + tid];
    else if (tid < 192) usqj[tid-128] = g_usq[b*NN + j0 + (tid-128)];
    __syncthreads();

    float acc[2][4][4];
    #pragma unroll
    for (int m = 0; m < 2; ++m)
        #pragma unroll
        for (int n = 0; n < 4; ++n)
            #pragma unroll
            for (int q = 0; q < 4; ++q) acc[m][n][q] = 0.f;

    #pragma unroll
    for (int kp = 0; kp < 4; ++kp) {
        int c8 = kp * 2;
        u32 aH[2][4], aL[2][4];
        #pragma unroll
        for (int mt = 0; mt < 2; ++mt) {
            int r = wy*32 + mt*16 + lr + (sub & 1)*8;
            int cc = c8 + (sub >> 1);
            ldmx4(ldm_addr(tiH, r, cc), aH[mt][0], aH[mt][1], aH[mt][2], aH[mt][3]);
            ldmx4(ldm_addr(tiL, r, cc), aL[mt][0], aL[mt][1], aL[mt][2], aL[mt][3]);
        }
        #pragma unroll
        for (int np = 0; np < 2; ++np) {
            int rb = wx*32 + np*16 + lr + (sub >> 1)*8;
            int cb = c8 + (sub & 1);
            u32 bh[4], bl[4];
            ldmx4(ldm_addr(tjH, rb, cb), bh[0], bh[1], bh[2], bh[3]);
            ldmx4(ldm_addr(tjL, rb, cb), bl[0], bl[1], bl[2], bl[3]);
            #pragma unroll
            for (int mt = 0; mt < 2; ++mt)
                #pragma unroll
                for (int t = 0; t < 2; ++t) {
                    float* d = acc[mt][np*2 + t];
                    mma16816(d, aH[mt], bh[2*t], bh[2*t+1]);
                    mma16816(d, aH[mt], bl[2*t], bl[2*t+1]);
                    mma16816(d, aL[mt], bh[2*t], bh[2*t+1]);
                }
        }
    }

    float s = 0.9f / __uint_as_float(g_maxbits);
    float s2 = s * s;
    float T = *temp, TH = fabsf(*thr);
    float* WgB = out + OFF_WGT + (size_t)b*NN*NN;
    #pragma unroll
    for (int mt = 0; mt < 2; ++mt) {
        int li = wy*32 + mt*16 + (lane >> 2);
        int gi0 = i0 + li, gi8 = gi0 + 8;
        float ui0 = usqi[li], ui8 = usqi[li + 8];
        size_t w0 = (size_t)gi0*NN + j0, w8 = (size_t)gi8*NN + j0;
        #pragma unroll
        for (int nt = 0; nt < 4; ++nt) {
            int c = wx*32 + nt*8 + 2*(lane & 3);
            float uj0 = usqj[c], uj1 = usqj[c + 1];
            float* d = acc[mt][nt];
            *(float2*)(WgB + w0 + c) = make_float2(sigw(d[0], ui0, uj0, s2, T, TH),
                                                   sigw(d[1], ui0, uj1, s2, T, TH));
            *(float2*)(WgB + w8 + c) = make_float2(sigw(d[2], ui8, uj0, s2, T, TH),
                                                   sigw(d[3], ui8, uj1, s2, T, TH));
        }
    }
}

extern "C" void kernel_launch(void* const* d_in, const int* in_sizes, int n_in,
                              void* d_out, int out_size) {
    const float* x    = (const float*)d_in[0];
    const float* A    = (const float*)d_in[1];
    const float* W    = (const float*)d_in[2];
    const float* bias = (const float*)d_in[3];
    const float* temp = (const float*)d_in[4];
    const float* thr  = (const float*)d_in[5];
    float* out = (float*)d_out;

    cudaFuncSetAttribute(k1x, cudaFuncAttributeMaxDynamicSharedMemorySize, 99328);
    cudaFuncSetAttribute(k5_mma, cudaFuncAttributeMaxDynamicSharedMemorySize, 50176);

    k0_xw<<<NB*NN/16, 256>>>(x, W);
    k1x<<<K1_BLOCKS + EDGE_BLOCKS, 256, 99328>>>(A, out);
    k1b3<<<128, 512>>>(bias, out);
    k5_mma<<<dim3(NN/64, NN/128, NB), 256, 50176>>>(temp, thr, out);
}